// round 2
// baseline (speedup 1.0000x reference)
#include <cuda_runtime.h>
#include <math.h>
#include <stdint.h>

#define BB 8
#define NN 16384
#define PP 512
#define DD 64
#define PTILE 64
#define NTILE 128
#define NCHUNKS 16
#define CHUNK (NN / NCHUNKS)   /* 1024 */
#define XPITCH 17              /* float4 units: 16 data + 1 pad */

// Scratch (__device__ globals: allocation-free rule)
__device__ float g_pt[DD * PP];                  // normalized prototypes, transposed [d][p]
__device__ float g_p2[PP];                       // ||p||^2 after normalization
__device__ float g_x2[BB * NN];                  // ||x||^2 per patch
__device__ unsigned long long g_packed[BB * PP]; // (sq_bits<<32) | n  (min-reduced)

// ---------------------------------------------------------------------------
__global__ void prep_kernel(const float* __restrict__ proto) {
    int t = blockIdx.x * blockDim.x + threadIdx.x;
    if (t < BB * PP) g_packed[t] = 0xFFFFFFFFFFFFFFFFull;

    int gw = t >> 5;          // prototype index
    int lane = t & 31;
    if (gw >= PP) return;

    float2 v = ((const float2*)(proto + gw * DD))[lane];
    float s = v.x * v.x + v.y * v.y;
    #pragma unroll
    for (int o = 16; o; o >>= 1) s += __shfl_xor_sync(0xFFFFFFFFu, s, o);
    float inv = 1.0f / fmaxf(sqrtf(s), 1e-12f);
    float a = v.x * inv, b = v.y * inv;
    g_pt[(2 * lane + 0) * PP + gw] = a;
    g_pt[(2 * lane + 1) * PP + gw] = b;
    float q = a * a + b * b;
    #pragma unroll
    for (int o = 16; o; o >>= 1) q += __shfl_xor_sync(0xFFFFFFFFu, q, o);
    if (lane == 0) g_p2[gw] = q;
}

// ---------------------------------------------------------------------------
__global__ void x2_kernel(const float* __restrict__ x) {
    int gw = (blockIdx.x * blockDim.x + threadIdx.x) >> 5;
    int lane = threadIdx.x & 31;
    if (gw >= BB * NN) return;
    float2 v = ((const float2*)(x + (size_t)gw * DD))[lane];
    float s = fmaf(v.x, v.x, v.y * v.y);
    #pragma unroll
    for (int o = 16; o; o >>= 1) s += __shfl_xor_sync(0xFFFFFFFFu, s, o);
    if (lane == 0) g_x2[gw] = s;
}

// ---------------------------------------------------------------------------
// Packed f32x2 helpers
// ---------------------------------------------------------------------------
__device__ __forceinline__ void ffma2(unsigned long long& d,
                                      unsigned long long a,
                                      unsigned long long b) {
    asm("fma.rn.f32x2 %0, %1, %2, %0;" : "+l"(d) : "l"(a), "l"(b));
}
__device__ __forceinline__ unsigned long long dup2(float a) {
    unsigned long long r;
    asm("mov.b64 %0, {%1, %1};" : "=l"(r) : "f"(a));
    return r;
}
__device__ __forceinline__ void unpack2(unsigned long long v, float& lo, float& hi) {
    asm("mov.b64 {%0, %1}, %2;" : "=f"(lo), "=f"(hi) : "l"(v));
}

// ---------------------------------------------------------------------------
// main: 128n x 64p tile, 256 threads, 4n x 8p microtile, f32x2-packed FMA.
// grid: (NCHUNKS, PP/PTILE, BB)
// ---------------------------------------------------------------------------
__global__ void __launch_bounds__(256, 2)
main_kernel(const float* __restrict__ x) {
    __shared__ float  ps[DD * PTILE];              // [d][p]  16 KB
    __shared__ float4 xs4[NTILE * XPITCH];         // [n][d/4 + pad]  ~34 KB
    __shared__ float  p2s[PTILE];
    __shared__ unsigned long long red[PTILE];

    const int bb = blockIdx.z;
    const int pt = blockIdx.y * PTILE;
    const int n0 = blockIdx.x * CHUNK;
    const int tid = threadIdx.x;
    const int tx = tid & 7;         // p group: p = pt + tx*8 + j   (j = 0..7)
    const int ty = tid >> 3;        // n group: n = pass + ty*4 + i (i = 0..3)

    // prototype tile: g_pt is [d][P] -> ps [d][64], coalesced copy
    for (int i = tid; i < DD * (PTILE / 4); i += 256) {
        int d = i / (PTILE / 4);
        int pg = i % (PTILE / 4);
        ((float4*)ps)[i] = ((const float4*)(g_pt + d * PP + pt))[pg];
    }
    if (tid < PTILE) {
        p2s[tid] = g_p2[pt + tid];
        red[tid] = 0xFFFFFFFFFFFFFFFFull;
    }

    const unsigned int ps_base =
        (unsigned int)__cvta_generic_to_shared(ps) + tx * 32;

    unsigned long long best[8];
    #pragma unroll
    for (int j = 0; j < 8; j++) best[j] = 0xFFFFFFFFFFFFFFFFull;

    const float* xb  = x + (size_t)bb * NN * DD;
    const float* x2b = g_x2 + bb * NN;

    for (int ns = 0; ns < CHUNK; ns += NTILE) {
        __syncthreads();
        // fill 128 x 64 x-subtile (2048 float4), 8 per thread, coalesced reads
        {
            const float4* src = (const float4*)(xb + (size_t)(n0 + ns) * DD);
            #pragma unroll
            for (int k = 0; k < 8; k++) {
                int idx = tid + k * 256;
                xs4[(idx >> 4) * XPITCH + (idx & 15)] = src[idx];
            }
        }
        __syncthreads();

        unsigned long long S[4][4];
        #pragma unroll
        for (int i = 0; i < 4; i++)
            #pragma unroll
            for (int jp = 0; jp < 4; jp++) S[i][jp] = 0ull;

        #pragma unroll
        for (int d4 = 0; d4 < DD / 4; d4++) {
            float4 af[4];
            #pragma unroll
            for (int i = 0; i < 4; i++) af[i] = xs4[(ty * 4 + i) * XPITCH + d4];

            #pragma unroll
            for (int dd = 0; dd < 4; dd++) {
                unsigned long long b0, b1, b2, b3;
                unsigned int ba = ps_base + (unsigned)((d4 * 4 + dd) * 256);
                asm("ld.shared.v2.b64 {%0,%1},[%2];"
                    : "=l"(b0), "=l"(b1) : "r"(ba));
                asm("ld.shared.v2.b64 {%0,%1},[%2];"
                    : "=l"(b2), "=l"(b3) : "r"(ba + 16));
                #pragma unroll
                for (int i = 0; i < 4; i++) {
                    float a = ((const float*)&af[i])[dd];
                    unsigned long long ad = dup2(a);
                    ffma2(S[i][0], ad, b0);
                    ffma2(S[i][1], ad, b1);
                    ffma2(S[i][2], ad, b2);
                    ffma2(S[i][3], ad, b3);
                }
            }
        }

        // min/argmin epilogue: 4 n's x 8 p's
        const int nbase = n0 + ns + ty * 4;
        #pragma unroll
        for (int i = 0; i < 4; i++) {
            float x2v = __ldg(&x2b[nbase + i]);
            unsigned long long nidx = (unsigned long long)(unsigned)(nbase + i);
            #pragma unroll
            for (int jp = 0; jp < 4; jp++) {
                float s0, s1;
                unpack2(S[i][jp], s0, s1);
                float p20 = p2s[tx * 8 + jp * 2 + 0];
                float p21 = p2s[tx * 8 + jp * 2 + 1];
                float sq0 = fmaxf(x2v - 2.0f * s0 + p20, 0.0f);
                float sq1 = fmaxf(x2v - 2.0f * s1 + p21, 0.0f);
                unsigned long long k0 =
                    ((unsigned long long)__float_as_uint(sq0) << 32) | nidx;
                unsigned long long k1 =
                    ((unsigned long long)__float_as_uint(sq1) << 32) | nidx;
                if (k0 < best[jp * 2 + 0]) best[jp * 2 + 0] = k0;
                if (k1 < best[jp * 2 + 1]) best[jp * 2 + 1] = k1;
            }
        }
    }

    __syncthreads();
    #pragma unroll
    for (int j = 0; j < 8; j++) atomicMin(&red[tx * 8 + j], best[j]);
    __syncthreads();
    if (tid < PTILE) atomicMin(&g_packed[bb * PP + pt + tid], red[tid]);
}

// ---------------------------------------------------------------------------
__global__ void unpack_kernel(float* __restrict__ out) {
    int t = blockIdx.x * blockDim.x + threadIdx.x;
    if (t >= BB * PP) return;
    unsigned long long k = g_packed[t];
    float sq = __uint_as_float((unsigned)(k >> 32));
    unsigned idx = (unsigned)(k & 0xFFFFFFFFu);
    out[t] = sqrtf(sq + 1e-8f);
    out[BB * PP + t] = (float)idx;
}

extern "C" void kernel_launch(void* const* d_in, const int* in_sizes, int n_in,
                              void* d_out, int out_size) {
    const float* x = (const float*)d_in[0];
    const float* proto = (const float*)d_in[1];
    float* out = (float*)d_out;

    prep_kernel<<<64, 256>>>(proto);
    x2_kernel<<<(BB * NN) / 8, 256>>>(x);
    dim3 grid(NCHUNKS, PP / PTILE, BB);
    main_kernel<<<grid, 256>>>(x);
    unpack_kernel<<<(BB * PP + 255) / 256, 256>>>(out);
}

// round 4
// speedup vs baseline: 1.4314x; 1.4314x over previous
#include <cuda_runtime.h>
#include <math.h>
#include <stdint.h>

#define BB 8
#define NN 16384
#define PP 512
#define DD 64
#define PT 128                  /* p per CTA (8 warps x 16) */
#define NSPLIT 8
#define NPER (NN / NSPLIT)      /* 2048 */
#define CHN 64                  /* n per chunk */
#define NCHUNK (NPER / CHN)     /* 32 */
#define PITCH 68                /* floats per n-row in smem (64 + 4 pad) */
#define XLO (CHN * PITCH)       /* float offset of lo block: 4352 */
#define X2OFF (2 * CHN * PITCH) /* float offset of x2 row: 8704 */

__device__ float g_phi[PP * DD];                 /* normalized protos, tf32 hi */
__device__ float g_plo[PP * DD];                 /* tf32-rounded residual */
__device__ float g_p2[PP];
__device__ unsigned long long g_packed[BB * PP];

__device__ __forceinline__ uint32_t tf32_bits(float x) {
    uint32_t h;
    asm("cvt.rna.tf32.f32 %0, %1;" : "=r"(h) : "f"(x));
    return h;
}

__device__ __forceinline__ void mma_tf32(float& d0, float& d1, float& d2, float& d3,
                                         uint32_t a0, uint32_t a1, uint32_t a2, uint32_t a3,
                                         uint32_t b0, uint32_t b1) {
    asm("mma.sync.aligned.m16n8k8.row.col.f32.tf32.tf32.f32 "
        "{%0,%1,%2,%3}, {%4,%5,%6,%7}, {%8,%9}, {%0,%1,%2,%3};"
        : "+f"(d0), "+f"(d1), "+f"(d2), "+f"(d3)
        : "r"(a0), "r"(a1), "r"(a2), "r"(a3), "r"(b0), "r"(b1));
}

/* ------------------------------------------------------------------ */
/* prep: normalize prototypes, exact hi/lo tf32 split ([p][d]), p2,
   reset packed buffer. 64 blocks x 256 threads (1 warp / prototype). */
__global__ void prep_kernel(const float* __restrict__ proto) {
    int t = blockIdx.x * blockDim.x + threadIdx.x;
    if (t < BB * PP) g_packed[t] = 0xFFFFFFFFFFFFFFFFull;

    int gw = t >> 5, lane = t & 31;
    if (gw >= PP) return;
    float2 v = ((const float2*)(proto + gw * DD))[lane];
    float s = v.x * v.x + v.y * v.y;
    #pragma unroll
    for (int o = 16; o; o >>= 1) s += __shfl_xor_sync(0xFFFFFFFFu, s, o);
    float inv = 1.0f / fmaxf(sqrtf(s), 1e-12f);
    float a = v.x * inv, b = v.y * inv;

    uint32_t ah = tf32_bits(a), bh = tf32_bits(b);
    uint32_t al = tf32_bits(a - __uint_as_float(ah));
    uint32_t bl = tf32_bits(b - __uint_as_float(bh));
    g_phi[gw * DD + 2 * lane + 0] = __uint_as_float(ah);
    g_phi[gw * DD + 2 * lane + 1] = __uint_as_float(bh);
    g_plo[gw * DD + 2 * lane + 0] = __uint_as_float(al);
    g_plo[gw * DD + 2 * lane + 1] = __uint_as_float(bl);

    float q = a * a + b * b;
    #pragma unroll
    for (int o = 16; o; o >>= 1) q += __shfl_xor_sync(0xFFFFFFFFu, q, o);
    if (lane == 0) g_p2[gw] = q;
}

/* ------------------------------------------------------------------ */
/* main: grid (NSPLIT, PP/PT, BB) x 256.  Warp w owns p rows
   [pb*128 + w*16, +16).  A (prototypes) register-resident; X streamed
   through smem in 64-n chunks with in-loader tf32 split + x2 reduce.  */
__global__ void __launch_bounds__(256, 2)
main_kernel(const float* __restrict__ x) {
    __shared__ __align__(16) uint32_t xs[2 * CHN * PITCH + CHN];

    const int tid = threadIdx.x;
    const int w = tid >> 5, lane = tid & 31;
    const int g = lane >> 2, tm4 = lane & 3;
    const int bb = blockIdx.z;
    const int p0 = blockIdx.y * PT + w * 16;
    const int n0 = blockIdx.x * NPER;

    /* preload A fragments (hi & lo) for this warp's 16 p-rows */
    uint32_t Ah[8][4], Al[8][4];
    {
        const float* ph = g_phi + (size_t)p0 * DD;
        const float* pl = g_plo + (size_t)p0 * DD;
        #pragma unroll
        for (int k8 = 0; k8 < 8; k8++) {
            int c0 = k8 * 8 + tm4;
            Ah[k8][0] = __float_as_uint(__ldg(ph + (size_t)g * DD + c0));
            Ah[k8][1] = __float_as_uint(__ldg(ph + (size_t)(g + 8) * DD + c0));
            Ah[k8][2] = __float_as_uint(__ldg(ph + (size_t)g * DD + c0 + 4));
            Ah[k8][3] = __float_as_uint(__ldg(ph + (size_t)(g + 8) * DD + c0 + 4));
            Al[k8][0] = __float_as_uint(__ldg(pl + (size_t)g * DD + c0));
            Al[k8][1] = __float_as_uint(__ldg(pl + (size_t)(g + 8) * DD + c0));
            Al[k8][2] = __float_as_uint(__ldg(pl + (size_t)g * DD + c0 + 4));
            Al[k8][3] = __float_as_uint(__ldg(pl + (size_t)(g + 8) * DD + c0 + 4));
        }
    }
    const float p2a = g_p2[p0 + g];
    const float p2b = g_p2[p0 + g + 8];

    unsigned long long best0 = 0xFFFFFFFFFFFFFFFFull;
    unsigned long long best1 = 0xFFFFFFFFFFFFFFFFull;

    const float4* xb = (const float4*)(x + ((size_t)bb * NN + n0) * DD);

    for (int it = 0; it < NCHUNK; it++) {
        __syncthreads();
        /* ---- load + split chunk; fused x2 row-sum ---- */
        {
            float s = 0.0f;
            const int row = tid >> 2;                 /* 0..63 */
            #pragma unroll
            for (int k = 0; k < 4; k++) {
                int idx = tid * 4 + k;                /* float4 index in chunk */
                int c4 = idx & 15;
                float4 v = xb[(size_t)it * CHN * (DD / 4) + idx];
                uint4 h, l;
                h.x = tf32_bits(v.x); l.x = tf32_bits(v.x - __uint_as_float(h.x));
                h.y = tf32_bits(v.y); l.y = tf32_bits(v.y - __uint_as_float(h.y));
                h.z = tf32_bits(v.z); l.z = tf32_bits(v.z - __uint_as_float(h.z));
                h.w = tf32_bits(v.w); l.w = tf32_bits(v.w - __uint_as_float(h.w));
                ((uint4*)xs)[row * (PITCH / 4) + c4] = h;
                ((uint4*)xs)[XLO / 4 + row * (PITCH / 4) + c4] = l;
                s = fmaf(v.x, v.x, s); s = fmaf(v.y, v.y, s);
                s = fmaf(v.z, v.z, s); s = fmaf(v.w, v.w, s);
            }
            s += __shfl_xor_sync(0xFFFFFFFFu, s, 1);
            s += __shfl_xor_sync(0xFFFFFFFFu, s, 2);
            if ((tid & 3) == 0) ((float*)xs)[X2OFF + row] = s;
        }
        __syncthreads();

        /* ---- compute: 8 n-subtiles, 4-term tf32 emulated fp32 GEMM ---- */
        #pragma unroll 1
        for (int sub = 0; sub < 8; sub++) {
            float d0 = 0.f, d1 = 0.f, d2 = 0.f, d3 = 0.f;
            const int nrow = sub * 8 + g;
            #pragma unroll
            for (int bsel = 0; bsel < 2; bsel++) {
                uint32_t B0[8], B1[8];
                const uint32_t* src = xs + bsel * XLO + nrow * PITCH;
                #pragma unroll
                for (int k8 = 0; k8 < 8; k8++) {
                    B0[k8] = src[k8 * 8 + tm4];
                    B1[k8] = src[k8 * 8 + tm4 + 4];
                }
                #pragma unroll
                for (int k8 = 0; k8 < 8; k8++)
                    mma_tf32(d0, d1, d2, d3,
                             Ah[k8][0], Ah[k8][1], Ah[k8][2], Ah[k8][3],
                             B0[k8], B1[k8]);
                #pragma unroll
                for (int k8 = 0; k8 < 8; k8++)
                    mma_tf32(d0, d1, d2, d3,
                             Al[k8][0], Al[k8][1], Al[k8][2], Al[k8][3],
                             B0[k8], B1[k8]);
            }
            /* epilogue: cols n = sub*8 + 2*tm4 + {0,1}; rows g, g+8 */
            const int nl = sub * 8 + 2 * tm4;
            const unsigned nglob = (unsigned)(n0 + it * CHN + nl);
            float x20 = ((const float*)xs)[X2OFF + nl];
            float x21 = ((const float*)xs)[X2OFF + nl + 1];
            float s00 = fmaxf(fmaf(d0, -2.0f, x20) + p2a, 0.0f);
            float s01 = fmaxf(fmaf(d1, -2.0f, x21) + p2a, 0.0f);
            float s10 = fmaxf(fmaf(d2, -2.0f, x20) + p2b, 0.0f);
            float s11 = fmaxf(fmaf(d3, -2.0f, x21) + p2b, 0.0f);
            unsigned long long k00 = ((unsigned long long)__float_as_uint(s00) << 32) | nglob;
            unsigned long long k01 = ((unsigned long long)__float_as_uint(s01) << 32) | (nglob + 1);
            unsigned long long k10 = ((unsigned long long)__float_as_uint(s10) << 32) | nglob;
            unsigned long long k11 = ((unsigned long long)__float_as_uint(s11) << 32) | (nglob + 1);
            if (k00 < best0) best0 = k00;
            if (k01 < best0) best0 = k01;
            if (k10 < best1) best1 = k10;
            if (k11 < best1) best1 = k11;
        }
    }

    /* reduce across the 4 threads sharing each p-row, then global min */
    {
        unsigned long long o;
        o = __shfl_xor_sync(0xFFFFFFFFu, best0, 1); if (o < best0) best0 = o;
        o = __shfl_xor_sync(0xFFFFFFFFu, best0, 2); if (o < best0) best0 = o;
        o = __shfl_xor_sync(0xFFFFFFFFu, best1, 1); if (o < best1) best1 = o;
        o = __shfl_xor_sync(0xFFFFFFFFu, best1, 2); if (o < best1) best1 = o;
        if (tm4 == 0) {
            atomicMin(&g_packed[bb * PP + p0 + g], best0);
            atomicMin(&g_packed[bb * PP + p0 + g + 8], best1);
        }
    }
}

/* ------------------------------------------------------------------ */
__global__ void unpack_kernel(float* __restrict__ out) {
    int t = blockIdx.x * blockDim.x + threadIdx.x;
    if (t >= BB * PP) return;
    unsigned long long k = g_packed[t];
    float sq = __uint_as_float((unsigned)(k >> 32));
    unsigned idx = (unsigned)(k & 0xFFFFFFFFu);
    out[t] = sqrtf(sq + 1e-8f);
    out[BB * PP + t] = (float)idx;
}

extern "C" void kernel_launch(void* const* d_in, const int* in_sizes, int n_in,
                              void* d_out, int out_size) {
    const float* x = (const float*)d_in[0];
    const float* proto = (const float*)d_in[1];
    float* out = (float*)d_out;

    prep_kernel<<<64, 256>>>(proto);
    dim3 grid(NSPLIT, PP / PT, BB);
    main_kernel<<<grid, 256>>>(x);
    unpack_kernel<<<(BB * PP + 255) / 256, 256>>>(out);
}

// round 5
// speedup vs baseline: 2.5926x; 1.8112x over previous
#include <cuda_runtime.h>
#include <cuda_fp16.h>
#include <math.h>
#include <stdint.h>

#define BB 8
#define NN 16384
#define PP 512
#define DD 64
#define PT 128                  /* p per CTA (8 warps x 16) */
#define NSPLIT 8
#define NPER (NN / NSPLIT)      /* 2048 */
#define CHN 64                  /* n per chunk */
#define NCHUNK (NPER / CHN)     /* 32 */
#define PIT_U 36                /* uints per n-row (32 data + 4 pad = 144B) */
#define XLOU (CHN * PIT_U)      /* uint offset of x1s block: 2304 */
#define X2U (2 * CHN * PIT_U)   /* uint offset of x2 row: 4608 */
#define RSCALE 4.8828125e-4f    /* 2^-11 */

__device__ unsigned g_ph0[PP * DD / 2];          /* p0  (fp16x2, [p][d]) */
__device__ unsigned g_ph1[PP * DD / 2];          /* p1s = fp16(2^11*(p-p0)) */
__device__ float g_p2[PP];
__device__ unsigned long long g_packed[BB * PP];

__device__ __forceinline__ void mma_f16(float& d0, float& d1, float& d2, float& d3,
                                        uint32_t a0, uint32_t a1, uint32_t a2, uint32_t a3,
                                        uint32_t b0, uint32_t b1) {
    asm("mma.sync.aligned.m16n8k16.row.col.f32.f16.f16.f32 "
        "{%0,%1,%2,%3}, {%4,%5,%6,%7}, {%8,%9}, {%0,%1,%2,%3};"
        : "+f"(d0), "+f"(d1), "+f"(d2), "+f"(d3)
        : "r"(a0), "r"(a1), "r"(a2), "r"(a3), "r"(b0), "r"(b1));
}

/* ------------------------------------------------------------------ */
/* prep: normalize prototypes, fp16 2-way split (residual pre-scaled by
   2^11), p2, reset packed buffer. One warp per prototype.             */
__global__ void prep_kernel(const float* __restrict__ proto) {
    int t = blockIdx.x * blockDim.x + threadIdx.x;
    if (t < BB * PP) g_packed[t] = 0xFFFFFFFFFFFFFFFFull;

    int gw = t >> 5, lane = t & 31;
    if (gw >= PP) return;
    float2 v = ((const float2*)(proto + gw * DD))[lane];
    float s = v.x * v.x + v.y * v.y;
    #pragma unroll
    for (int o = 16; o; o >>= 1) s += __shfl_xor_sync(0xFFFFFFFFu, s, o);
    float inv = 1.0f / fmaxf(sqrtf(s), 1e-12f);
    float a = v.x * inv, b = v.y * inv;

    __half2 h = __floats2half2_rn(a, b);
    float2 f = __half22float2(h);
    __half2 r = __floats2half2_rn((a - f.x) * 2048.0f, (b - f.y) * 2048.0f);
    g_ph0[gw * 32 + lane] = *(const unsigned*)&h;
    g_ph1[gw * 32 + lane] = *(const unsigned*)&r;

    float q = a * a + b * b;
    #pragma unroll
    for (int o = 16; o; o >>= 1) q += __shfl_xor_sync(0xFFFFFFFFu, q, o);
    if (lane == 0) g_p2[gw] = q;
}

/* ------------------------------------------------------------------ */
/* main: grid (NSPLIT, PP/PT, BB) x 256.  Warp w owns 16 p-rows; A
   (prototype) fragments register-resident; X streamed through smem in
   64-n chunks as fp16 hi + scaled-residual, with fused x2 reduce.     */
__global__ void __launch_bounds__(256, 2)
main_kernel(const float* __restrict__ x) {
    __shared__ __align__(16) unsigned xs[2 * CHN * PIT_U + CHN];

    const int tid = threadIdx.x;
    const int w = tid >> 5, lane = tid & 31;
    const int g = lane >> 2, tm4 = lane & 3;
    const int bb = blockIdx.z;
    const int p0 = blockIdx.y * PT + w * 16;
    const int n0 = blockIdx.x * NPER;

    /* preload A fragments: p0 / p1s for this warp's 16 p-rows.
       reg r of k-step k8: r0=(row g, u k8*8+tm4) r1=(g+8) r2=(+4) r3=(g+8,+4) */
    uint32_t A0[4][4], A1[4][4];
    {
        const unsigned* h0 = g_ph0 + (size_t)p0 * 32;
        const unsigned* h1 = g_ph1 + (size_t)p0 * 32;
        #pragma unroll
        for (int k8 = 0; k8 < 4; k8++) {
            int c = k8 * 8 + tm4;
            A0[k8][0] = __ldg(h0 + (size_t)g * 32 + c);
            A0[k8][1] = __ldg(h0 + (size_t)(g + 8) * 32 + c);
            A0[k8][2] = __ldg(h0 + (size_t)g * 32 + c + 4);
            A0[k8][3] = __ldg(h0 + (size_t)(g + 8) * 32 + c + 4);
            A1[k8][0] = __ldg(h1 + (size_t)g * 32 + c);
            A1[k8][1] = __ldg(h1 + (size_t)(g + 8) * 32 + c);
            A1[k8][2] = __ldg(h1 + (size_t)g * 32 + c + 4);
            A1[k8][3] = __ldg(h1 + (size_t)(g + 8) * 32 + c + 4);
        }
    }
    const float p2a = g_p2[p0 + g];
    const float p2b = g_p2[p0 + g + 8];

    unsigned long long best0 = 0xFFFFFFFFFFFFFFFFull;
    unsigned long long best1 = 0xFFFFFFFFFFFFFFFFull;

    const float4* xb = (const float4*)(x + ((size_t)bb * NN + n0) * DD);

    for (int it = 0; it < NCHUNK; it++) {
        __syncthreads();
        /* ---- load chunk: fp16 split (residual x 2^11) + fused x2 ---- */
        {
            float s = 0.0f;
            const int row = tid >> 2;
            #pragma unroll
            for (int k = 0; k < 4; k++) {
                int idx = tid * 4 + k;
                int c4 = idx & 15;             /* float4 index within row */
                float4 v = xb[(size_t)it * CHN * (DD / 4) + idx];
                __half2 h0 = __floats2half2_rn(v.x, v.y);
                __half2 h1 = __floats2half2_rn(v.z, v.w);
                float2 f0 = __half22float2(h0);
                float2 f1 = __half22float2(h1);
                __half2 r0 = __floats2half2_rn((v.x - f0.x) * 2048.0f,
                                               (v.y - f0.y) * 2048.0f);
                __half2 r1 = __floats2half2_rn((v.z - f1.x) * 2048.0f,
                                               (v.w - f1.y) * 2048.0f);
                unsigned ubase = row * PIT_U + c4 * 2;
                xs[ubase + 0] = *(const unsigned*)&h0;
                xs[ubase + 1] = *(const unsigned*)&h1;
                xs[XLOU + ubase + 0] = *(const unsigned*)&r0;
                xs[XLOU + ubase + 1] = *(const unsigned*)&r1;
                s = fmaf(v.x, v.x, s); s = fmaf(v.y, v.y, s);
                s = fmaf(v.z, v.z, s); s = fmaf(v.w, v.w, s);
            }
            s += __shfl_xor_sync(0xFFFFFFFFu, s, 1);
            s += __shfl_xor_sync(0xFFFFFFFFu, s, 2);
            if ((tid & 3) == 0) ((float*)xs)[X2U + row] = s;
        }
        __syncthreads();

        /* ---- 8 n-subtiles: 3-term fp16 emulated fp32 GEMM ---- */
        #pragma unroll 1
        for (int sub = 0; sub < 8; sub++) {
            const int nrow = sub * 8 + g;
            uint32_t B0[4][2], B1[4][2];
            const unsigned* s0 = xs + nrow * PIT_U;
            const unsigned* s1 = xs + XLOU + nrow * PIT_U;
            #pragma unroll
            for (int k8 = 0; k8 < 4; k8++) {
                B0[k8][0] = s0[k8 * 8 + tm4];
                B0[k8][1] = s0[k8 * 8 + tm4 + 4];
                B1[k8][0] = s1[k8 * 8 + tm4];
                B1[k8][1] = s1[k8 * 8 + tm4 + 4];
            }
            float d0 = 0.f, d1 = 0.f, d2 = 0.f, d3 = 0.f;   /* p0.x0 */
            float e0 = 0.f, e1 = 0.f, e2 = 0.f, e3 = 0.f;   /* scaled terms */
            #pragma unroll
            for (int k8 = 0; k8 < 4; k8++)
                mma_f16(d0, d1, d2, d3,
                        A0[k8][0], A0[k8][1], A0[k8][2], A0[k8][3],
                        B0[k8][0], B0[k8][1]);
            #pragma unroll
            for (int k8 = 0; k8 < 4; k8++)
                mma_f16(e0, e1, e2, e3,
                        A0[k8][0], A0[k8][1], A0[k8][2], A0[k8][3],
                        B1[k8][0], B1[k8][1]);
            #pragma unroll
            for (int k8 = 0; k8 < 4; k8++)
                mma_f16(e0, e1, e2, e3,
                        A1[k8][0], A1[k8][1], A1[k8][2], A1[k8][3],
                        B0[k8][0], B0[k8][1]);

            float t0 = fmaf(e0, RSCALE, d0);
            float t1 = fmaf(e1, RSCALE, d1);
            float t2 = fmaf(e2, RSCALE, d2);
            float t3 = fmaf(e3, RSCALE, d3);

            /* epilogue: cols n = sub*8 + 2*tm4 + {0,1}; rows g, g+8 */
            const int nl = sub * 8 + 2 * tm4;
            const unsigned nglob = (unsigned)(n0 + it * CHN + nl);
            float x20 = ((const float*)xs)[X2U + nl];
            float x21 = ((const float*)xs)[X2U + nl + 1];
            float s00 = fmaxf(fmaf(t0, -2.0f, x20) + p2a, 0.0f);
            float s01 = fmaxf(fmaf(t1, -2.0f, x21) + p2a, 0.0f);
            float s10 = fmaxf(fmaf(t2, -2.0f, x20) + p2b, 0.0f);
            float s11 = fmaxf(fmaf(t3, -2.0f, x21) + p2b, 0.0f);
            unsigned long long k00 = ((unsigned long long)__float_as_uint(s00) << 32) | nglob;
            unsigned long long k01 = ((unsigned long long)__float_as_uint(s01) << 32) | (nglob + 1);
            unsigned long long k10 = ((unsigned long long)__float_as_uint(s10) << 32) | nglob;
            unsigned long long k11 = ((unsigned long long)__float_as_uint(s11) << 32) | (nglob + 1);
            if (k00 < best0) best0 = k00;
            if (k01 < best0) best0 = k01;
            if (k10 < best1) best1 = k10;
            if (k11 < best1) best1 = k11;
        }
    }

    /* reduce across the 4 threads sharing each p-row, then global min */
    {
        unsigned long long o;
        o = __shfl_xor_sync(0xFFFFFFFFu, best0, 1); if (o < best0) best0 = o;
        o = __shfl_xor_sync(0xFFFFFFFFu, best0, 2); if (o < best0) best0 = o;
        o = __shfl_xor_sync(0xFFFFFFFFu, best1, 1); if (o < best1) best1 = o;
        o = __shfl_xor_sync(0xFFFFFFFFu, best1, 2); if (o < best1) best1 = o;
        if (tm4 == 0) {
            atomicMin(&g_packed[bb * PP + p0 + g], best0);
            atomicMin(&g_packed[bb * PP + p0 + g + 8], best1);
        }
    }
}

/* ------------------------------------------------------------------ */
__global__ void unpack_kernel(float* __restrict__ out) {
    int t = blockIdx.x * blockDim.x + threadIdx.x;
    if (t >= BB * PP) return;
    unsigned long long k = g_packed[t];
    float sq = __uint_as_float((unsigned)(k >> 32));
    unsigned idx = (unsigned)(k & 0xFFFFFFFFu);
    out[t] = sqrtf(sq + 1e-8f);
    out[BB * PP + t] = (float)idx;
}

extern "C" void kernel_launch(void* const* d_in, const int* in_sizes, int n_in,
                              void* d_out, int out_size) {
    const float* x = (const float*)d_in[0];
    const float* proto = (const float*)d_in[1];
    float* out = (float*)d_out;

    prep_kernel<<<64, 256>>>(proto);
    dim3 grid(NSPLIT, PP / PT, BB);
    main_kernel<<<grid, 256>>>(x);
    unpack_kernel<<<(BB * PP + 255) / 256, 256>>>(out);
}